// round 6
// baseline (speedup 1.0000x reference)
#include <cuda_runtime.h>
#include <cuda_fp16.h>
#include <cstdint>
#include <math.h>

#define BATCH 2
#define SEQ   2048
#define EMB   1024
#define HEADS 16
#define HDIM  64
#define F3    3072
#define MROWS 4096

#define XN (MROWS*EMB)
#define WN (F3*EMB)
#define QN (BATCH*HEADS*SEQ*HDIM)

// log2(e)/32: folds the 1/sqrt(EMB) scale and exp->ex2 base change into Q
#define QSCALE 0.045084220027780106f
#define ONE2   0x3C003C00u   // packed fp16 {1.0, 1.0}

// ---------------- device scratch ----------------
__device__ __half g_x16[XN], g_w16[WN];
__device__ __half g_q16[QN], g_k16[QN], g_v16[QN];   // [B,H,N,D]

// ---------------- helpers ----------------
__device__ __forceinline__ uint32_t smem_u32(const void* p) {
    uint32_t a;
    asm("{ .reg .u64 t; cvta.to.shared.u64 t, %1; cvt.u32.u64 %0, t; }" : "=r"(a) : "l"(p));
    return a;
}
#define CP16(dst, src) asm volatile("cp.async.cg.shared.global [%0], [%1], 16;" :: "r"(dst), "l"(src))
#define CP_COMMIT()    asm volatile("cp.async.commit_group;" ::: "memory")
#define CP_WAIT(n)     asm volatile("cp.async.wait_group %0;" :: "n"(n) : "memory")

__device__ __forceinline__ void ldsm4(uint32_t* r, uint32_t a) {
    asm volatile("ldmatrix.sync.aligned.m8n8.x4.shared.b16 {%0,%1,%2,%3}, [%4];"
        : "=r"(r[0]), "=r"(r[1]), "=r"(r[2]), "=r"(r[3]) : "r"(a));
}
__device__ __forceinline__ void ldsm4t(uint32_t* r, uint32_t a) {
    asm volatile("ldmatrix.sync.aligned.m8n8.x4.trans.shared.b16 {%0,%1,%2,%3}, [%4];"
        : "=r"(r[0]), "=r"(r[1]), "=r"(r[2]), "=r"(r[3]) : "r"(a));
}
__device__ __forceinline__ void mma_f16(float* d, const uint32_t* a, uint32_t b0, uint32_t b1) {
    asm volatile("mma.sync.aligned.m16n8k16.row.col.f32.f16.f16.f32 "
        "{%0,%1,%2,%3}, {%4,%5,%6,%7}, {%8,%9}, {%0,%1,%2,%3};"
        : "+f"(d[0]), "+f"(d[1]), "+f"(d[2]), "+f"(d[3])
        : "r"(a[0]), "r"(a[1]), "r"(a[2]), "r"(a[3]), "r"(b0), "r"(b1));
}
__device__ __forceinline__ uint32_t pack_h2(float a, float b) {
    __half2 t = __floats2half2_rn(a, b);
    return *(uint32_t*)&t;
}
__device__ __forceinline__ uint32_t ex2h2(uint32_t x) {
    uint32_t y;
    asm("ex2.approx.f16x2 %0, %1;" : "=r"(y) : "r"(x));
    return y;
}

// ---------------- fp32 -> fp16 convert kernels ----------------
__global__ __launch_bounds__(256) void cvt_x(const float* __restrict__ src) {
    int i = blockIdx.x * 256 + threadIdx.x;
    if (i < XN / 2) {
        float2 v = ((const float2*)src)[i];
        ((__half2*)g_x16)[i] = __floats2half2_rn(v.x, v.y);
    }
}
__global__ __launch_bounds__(256) void cvt_w(const float* __restrict__ src) {
    int i = blockIdx.x * 256 + threadIdx.x;
    if (i < WN / 2) {
        float2 v = ((const float2*)src)[i];
        ((__half2*)g_w16)[i] = __floats2half2_rn(v.x, v.y);
    }
}

// ---------------- QKV GEMM: mma.sync fp16, 3-stage pipeline ----------------
// C[m,f] = X[m,:].W[f,:] + bias[f]. CTA 128x128, BK=32, 32 chunks, 1 sync/chunk.
#define GTILE_B (128*80)             // 10240 per matrix per stage
#define GSTAGE_B (2*GTILE_B)
#define GEMM_SMEM (3*GSTAGE_B)       // 61440

__global__ __launch_bounds__(256, 2) void qkv_gemm_mma(const float* __restrict__ bias) {
    extern __shared__ char sm[];
    const uint32_t sbase = smem_u32(sm);
    const int tid = threadIdx.x, lane = tid & 31, wid = tid >> 5;
    const int wm = wid >> 2, wn = wid & 3;           // 2x4 warp grid, warp tile 64x32
    const int g = lane >> 2, qd = (lane & 3) * 2;
    const int f0 = blockIdx.x * 128, m0 = blockIdx.y * 128;

    float acc[4][4][4];
    #pragma unroll
    for (int i = 0; i < 4; i++)
        #pragma unroll
        for (int j = 0; j < 4; j++)
            #pragma unroll
            for (int e = 0; e < 4; e++) acc[i][j][e] = 0.f;

    auto load_chunk = [&](int c) {
        const int k0 = c * 32;
        const uint32_t ab = sbase + (c % 3) * GSTAGE_B;
        const uint32_t bb = ab + GTILE_B;
        #pragma unroll
        for (int i = 0; i < 2; i++) {
            const int l = tid + i * 256;
            const int row = l >> 2, c16 = l & 3;
            CP16(ab + row * 80 + c16 * 16, g_x16 + (size_t)(m0 + row) * EMB + k0 + c16 * 8);
            CP16(bb + row * 80 + c16 * 16, g_w16 + (size_t)(f0 + row) * EMB + k0 + c16 * 8);
        }
    };

    load_chunk(0); CP_COMMIT();
    load_chunk(1); CP_COMMIT();

    for (int c = 0; c < 32; c++) {
        if (c < 31) { CP_WAIT(1); } else { CP_WAIT(0); }
        __syncthreads();
        if (c + 2 < 32) { load_chunk(c + 2); CP_COMMIT(); }

        const uint32_t ab = sbase + (c % 3) * GSTAGE_B;
        const uint32_t bb = ab + GTILE_B;
        #pragma unroll
        for (int kk = 0; kk < 2; kk++) {
            uint32_t afr[4][4];
            #pragma unroll
            for (int mf = 0; mf < 4; mf++)
                ldsm4(afr[mf], ab + (wm * 64 + mf * 16 + (lane & 15)) * 80 + kk * 32 + (lane >> 4) * 16);
            #pragma unroll
            for (int np = 0; np < 2; np++) {
                uint32_t t[4];
                ldsm4(t, bb + (wn * 32 + np * 16 + (lane & 15)) * 80 + kk * 32 + (lane >> 4) * 16);
                #pragma unroll
                for (int mf = 0; mf < 4; mf++) {
                    mma_f16(acc[mf][np * 2 + 0], afr[mf], t[0], t[2]);
                    mma_f16(acc[mf][np * 2 + 1], afr[mf], t[1], t[3]);
                }
            }
        }
    }

    // epilogue: bias, route to Q/K/V fp16 [B,H,N,D]; Q scaled by log2e/32
    const int sec = f0 >> 10;
    const int bb_ = m0 >> 11;
    __half* dst = (sec == 0) ? g_q16 : (sec == 1) ? g_k16 : g_v16;
    const float sc = (sec == 0) ? QSCALE : 1.0f;
    float bv[4][2];
    #pragma unroll
    for (int nf = 0; nf < 4; nf++) {
        const int fc = f0 + wn * 32 + nf * 8 + qd;
        bv[nf][0] = bias[fc]; bv[nf][1] = bias[fc + 1];
    }
    #pragma unroll
    for (int mf = 0; mf < 4; mf++) {
        const int n0 = (m0 & (SEQ - 1)) + wm * 64 + mf * 16 + g;
        const int n1 = n0 + 8;
        #pragma unroll
        for (int nf = 0; nf < 4; nf++) {
            const int fc = f0 + wn * 32 + nf * 8 + qd;
            const int e = fc & (EMB - 1);
            const int hh = e >> 6, d = e & 63;
            const size_t i0 = (((size_t)(bb_ * HEADS + hh)) * SEQ + n0) * HDIM + d;
            const size_t i1 = (((size_t)(bb_ * HEADS + hh)) * SEQ + n1) * HDIM + d;
            *(uint32_t*)(dst + i0) = pack_h2((acc[mf][nf][0] + bv[nf][0]) * sc,
                                             (acc[mf][nf][1] + bv[nf][1]) * sc);
            *(uint32_t*)(dst + i1) = pack_h2((acc[mf][nf][2] + bv[nf][0]) * sc,
                                             (acc[mf][nf][3] + bv[nf][1]) * sc);
        }
    }
}

// ---------------- Attention: fp16 flash, packed-ex2 softmax, ones-col lsum ----------------
// CTA: 128 q-rows, 8 warps (16 q each). 64-key tiles, 3-stage K/V pipeline, 1 sync/tile.
#define AP_B 144                     // pitch: 72 fp16 = 144 B
#define QT_B (128*AP_B)              // 18432
#define KT_B (64*AP_B)               // 9216
#define ATTN_SMEM (QT_B + 6*KT_B)    // 73728

__global__ __launch_bounds__(256, 2) void attn_mma(float* __restrict__ out) {
    extern __shared__ char sm[];
    const uint32_t sbase = smem_u32(sm);
    const int tid = threadIdx.x, lane = tid & 31, wid = tid >> 5;
    const int g = lane >> 2, qd = (lane & 3) * 2;
    const int b = blockIdx.z, h = blockIdx.y, q0 = blockIdx.x * 128;
    const size_t ho = ((size_t)(b * HEADS + h)) * SEQ * HDIM;
    const __half* qg = g_q16 + ho + (size_t)q0 * HDIM;
    const __half* kg = g_k16 + ho;
    const __half* vg = g_v16 + ho;

    auto load_tile = [&](int jt) {
        const int buf = jt % 3;
        const uint32_t Kb = sbase + QT_B + buf * KT_B;
        const uint32_t Vb = sbase + QT_B + 3 * KT_B + buf * KT_B;
        const int base = jt * 64;
        #pragma unroll
        for (int i = 0; i < 2; i++) {
            const int l = tid + i * 256;
            const int row = l >> 3, cc = l & 7;
            const size_t go = (size_t)(base + row) * HDIM + cc * 8;
            CP16(Kb + row * AP_B + cc * 16, kg + go);
            CP16(Vb + row * AP_B + cc * 16, vg + go);
        }
    };

    // Q (once) + tile 0 in group 0; tile 1 in group 1
    #pragma unroll
    for (int i = 0; i < 4; i++) {
        const int l = tid + i * 256;
        const int row = l >> 3, cc = l & 7;
        CP16(sbase + row * AP_B + cc * 16, qg + (size_t)row * HDIM + cc * 8);
    }
    load_tile(0); CP_COMMIT();
    load_tile(1); CP_COMMIT();

    float o[8][4];
    #pragma unroll
    for (int nf = 0; nf < 8; nf++)
        #pragma unroll
        for (int e = 0; e < 4; e++) o[nf][e] = 0.f;
    float ls[4] = {0.f, 0.f, 0.f, 0.f};
    uint32_t qf[4][4];

    for (int jt = 0; jt < SEQ / 64; jt++) {
        if (jt < SEQ / 64 - 1) { CP_WAIT(1); } else { CP_WAIT(0); }
        __syncthreads();
        if (jt + 2 < SEQ / 64) { load_tile(jt + 2); CP_COMMIT(); }
        if (jt == 0) {
            #pragma unroll
            for (int kk = 0; kk < 4; kk++)
                ldsm4(qf[kk], sbase + (wid * 16 + (lane & 15)) * AP_B + kk * 32 + (lane >> 4) * 16);
        }
        const int buf = jt % 3;
        const uint32_t Kb = sbase + QT_B + buf * KT_B;
        const uint32_t Vb = sbase + QT_B + 3 * KT_B + buf * KT_B;

        // S = Q K^T
        float s[8][4];
        #pragma unroll
        for (int nf = 0; nf < 8; nf++)
            #pragma unroll
            for (int e = 0; e < 4; e++) s[nf][e] = 0.f;
        #pragma unroll
        for (int kk = 0; kk < 4; kk++) {
            #pragma unroll
            for (int np = 0; np < 4; np++) {
                uint32_t t[4];
                ldsm4(t, Kb + (np * 16 + (lane & 15)) * AP_B + kk * 32 + (lane >> 4) * 16);
                mma_f16(s[np * 2 + 0], qf[kk], t[0], t[2]);
                mma_f16(s[np * 2 + 1], qf[kk], t[1], t[3]);
            }
        }

        // p = 2^s in packed fp16; lsum via ones-column mma; PV
        #pragma unroll
        for (int kk2 = 0; kk2 < 4; kk2++) {
            uint32_t ph[4];
            ph[0] = ex2h2(pack_h2(s[2 * kk2][0],     s[2 * kk2][1]));
            ph[1] = ex2h2(pack_h2(s[2 * kk2][2],     s[2 * kk2][3]));
            ph[2] = ex2h2(pack_h2(s[2 * kk2 + 1][0], s[2 * kk2 + 1][1]));
            ph[3] = ex2h2(pack_h2(s[2 * kk2 + 1][2], s[2 * kk2 + 1][3]));

            mma_f16(ls, ph, ONE2, ONE2);   // row sums of exactly the fp16 P used below

            const uint32_t vrow = (kk2 * 16 + (lane & 7) + ((lane >> 3) & 1) * 8) * AP_B;
            #pragma unroll
            for (int db = 0; db < 4; db++) {
                const uint32_t vcol = (db * 16 + (lane >> 4) * 8) * 2;
                uint32_t th[4];
                ldsm4t(th, Vb + vrow + vcol);
                mma_f16(o[db * 2 + 0], ph, th[0], th[1]);
                mma_f16(o[db * 2 + 1], ph, th[2], th[3]);
            }
        }
    }

    // ls[0] = full row sum for row g, ls[2] for row g+8 (all cols identical)
    const float inv0 = 1.0f / ls[0], inv1 = 1.0f / ls[2];
    const int r0 = q0 + wid * 16 + g;
    float* op0 = out + ((size_t)(b * SEQ + r0)) * EMB + h * HDIM;
    float* op1 = op0 + (size_t)8 * EMB;
    #pragma unroll
    for (int nf = 0; nf < 8; nf++) {
        const int d = nf * 8 + qd;
        float2 v;
        v.x = o[nf][0] * inv0; v.y = o[nf][1] * inv0;
        *(float2*)(op0 + d) = v;
        v.x = o[nf][2] * inv1; v.y = o[nf][3] * inv1;
        *(float2*)(op1 + d) = v;
    }
}

// ---------------- launcher ----------------
extern "C" void kernel_launch(void* const* d_in, const int* in_sizes, int n_in,
                              void* d_out, int out_size)
{
    const float* x    = (const float*)d_in[0];
    const float* w    = (const float*)d_in[1];
    const float* bias = (const float*)d_in[2];
    float* out = (float*)d_out;

    cvt_x<<<XN / 512, 256>>>(x);
    cvt_w<<<WN / 512, 256>>>(w);

    cudaFuncSetAttribute(qkv_gemm_mma, cudaFuncAttributeMaxDynamicSharedMemorySize, GEMM_SMEM);
    dim3 g1(F3 / 128, MROWS / 128);   // (24, 32)
    qkv_gemm_mma<<<g1, 256, GEMM_SMEM>>>(bias);

    cudaFuncSetAttribute(attn_mma, cudaFuncAttributeMaxDynamicSharedMemorySize, ATTN_SMEM);
    dim3 g2(SEQ / 128, HEADS, BATCH); // (16, 16, 2)
    attn_mma<<<g2, 256, ATTN_SMEM>>>(out);
}

// round 8
// speedup vs baseline: 1.1198x; 1.1198x over previous
#include <cuda_runtime.h>
#include <cuda_fp16.h>
#include <cstdint>
#include <math.h>

#define BATCH 2
#define SEQ   2048
#define EMB   1024
#define HEADS 16
#define HDIM  64
#define F3    3072
#define MROWS 4096

#define XN (MROWS*EMB)
#define WN (F3*EMB)
#define QN (BATCH*HEADS*SEQ*HDIM)

// log2(e)/32: folds the 1/sqrt(EMB) scale and exp->ex2 base change into Q
#define QSCALE 0.045084220027780106f
#define ONE2   0x3C003C00u   // packed fp16 {1.0, 1.0}

// ---------------- device scratch ----------------
__device__ __half g_x16[XN], g_w16[WN];
__device__ __half g_q16[QN], g_k16[QN], g_v16[QN];   // [B,H,N,D]

// ---------------- helpers ----------------
__device__ __forceinline__ uint32_t smem_u32(const void* p) {
    uint32_t a;
    asm("{ .reg .u64 t; cvta.to.shared.u64 t, %1; cvt.u32.u64 %0, t; }" : "=r"(a) : "l"(p));
    return a;
}
#define CP16(dst, src) asm volatile("cp.async.cg.shared.global [%0], [%1], 16;" :: "r"(dst), "l"(src))
#define CP_COMMIT()    asm volatile("cp.async.commit_group;" ::: "memory")
#define CP_WAIT(n)     asm volatile("cp.async.wait_group %0;" :: "n"(n) : "memory")

__device__ __forceinline__ void ldsm4(uint32_t* r, uint32_t a) {
    asm volatile("ldmatrix.sync.aligned.m8n8.x4.shared.b16 {%0,%1,%2,%3}, [%4];"
        : "=r"(r[0]), "=r"(r[1]), "=r"(r[2]), "=r"(r[3]) : "r"(a));
}
__device__ __forceinline__ void ldsm4t(uint32_t* r, uint32_t a) {
    asm volatile("ldmatrix.sync.aligned.m8n8.x4.trans.shared.b16 {%0,%1,%2,%3}, [%4];"
        : "=r"(r[0]), "=r"(r[1]), "=r"(r[2]), "=r"(r[3]) : "r"(a));
}
__device__ __forceinline__ void mma_f16(float* d, const uint32_t* a, uint32_t b0, uint32_t b1) {
    asm volatile("mma.sync.aligned.m16n8k16.row.col.f32.f16.f16.f32 "
        "{%0,%1,%2,%3}, {%4,%5,%6,%7}, {%8,%9}, {%0,%1,%2,%3};"
        : "+f"(d[0]), "+f"(d[1]), "+f"(d[2]), "+f"(d[3])
        : "r"(a[0]), "r"(a[1]), "r"(a[2]), "r"(a[3]), "r"(b0), "r"(b1));
}
__device__ __forceinline__ uint32_t pack_h2(float a, float b) {
    __half2 t = __floats2half2_rn(a, b);
    return *(uint32_t*)&t;
}
__device__ __forceinline__ uint32_t ex2h2(uint32_t x) {
    uint32_t y;
    asm("ex2.approx.f16x2 %0, %1;" : "=r"(y) : "r"(x));
    return y;
}

// ---------------- fp32 -> fp16 convert kernels ----------------
__global__ __launch_bounds__(256) void cvt_x(const float* __restrict__ src) {
    int i = blockIdx.x * 256 + threadIdx.x;
    if (i < XN / 2) {
        float2 v = ((const float2*)src)[i];
        ((__half2*)g_x16)[i] = __floats2half2_rn(v.x, v.y);
    }
}
__global__ __launch_bounds__(256) void cvt_w(const float* __restrict__ src) {
    int i = blockIdx.x * 256 + threadIdx.x;
    if (i < WN / 2) {
        float2 v = ((const float2*)src)[i];
        ((__half2*)g_w16)[i] = __floats2half2_rn(v.x, v.y);
    }
}

// ---------------- QKV GEMM: 128x64 CTA, 4 warps, 3-stage, 4 CTAs/SM ----------------
#define GA_B (128*80)                // 10240 (A tile per stage)
#define GB_B (64*80)                 // 5120  (B tile per stage)
#define GSTAGE (GA_B + GB_B)         // 15360
#define GEMM_SMEM (3*GSTAGE)         // 46080

__global__ __launch_bounds__(128, 4) void qkv_gemm_mma(const float* __restrict__ bias) {
    extern __shared__ char sm[];
    const uint32_t sbase = smem_u32(sm);
    const int tid = threadIdx.x, lane = tid & 31, wid = tid >> 5;
    const int wm = wid >> 1, wn = wid & 1;           // 2x2 warp grid, warp tile 64x32
    const int g = lane >> 2, qd = (lane & 3) * 2;
    const int f0 = blockIdx.x * 64, m0 = blockIdx.y * 128;

    float acc[4][4][4];
    #pragma unroll
    for (int i = 0; i < 4; i++)
        #pragma unroll
        for (int j = 0; j < 4; j++)
            #pragma unroll
            for (int e = 0; e < 4; e++) acc[i][j][e] = 0.f;

    auto load_chunk = [&](int c) {
        const int k0 = c * 32;
        const uint32_t ab = sbase + (c % 3) * GSTAGE;
        const uint32_t bb = ab + GA_B;
        #pragma unroll
        for (int i = 0; i < 4; i++) {
            const int l = tid + i * 128;
            const int row = l >> 2, c16 = l & 3;
            CP16(ab + row * 80 + c16 * 16, g_x16 + (size_t)(m0 + row) * EMB + k0 + c16 * 8);
        }
        #pragma unroll
        for (int i = 0; i < 2; i++) {
            const int l = tid + i * 128;
            const int row = l >> 2, c16 = l & 3;
            CP16(bb + row * 80 + c16 * 16, g_w16 + (size_t)(f0 + row) * EMB + k0 + c16 * 8);
        }
    };

    load_chunk(0); CP_COMMIT();
    load_chunk(1); CP_COMMIT();

    for (int c = 0; c < 32; c++) {
        if (c < 31) { CP_WAIT(1); } else { CP_WAIT(0); }
        __syncthreads();
        if (c + 2 < 32) { load_chunk(c + 2); CP_COMMIT(); }

        const uint32_t ab = sbase + (c % 3) * GSTAGE;
        const uint32_t bb = ab + GA_B;
        #pragma unroll
        for (int kk = 0; kk < 2; kk++) {
            uint32_t afr[4][4];
            #pragma unroll
            for (int mf = 0; mf < 4; mf++)
                ldsm4(afr[mf], ab + (wm * 64 + mf * 16 + (lane & 15)) * 80 + kk * 32 + (lane >> 4) * 16);
            #pragma unroll
            for (int np = 0; np < 2; np++) {
                uint32_t t[4];
                ldsm4(t, bb + (wn * 32 + np * 16 + (lane & 15)) * 80 + kk * 32 + (lane >> 4) * 16);
                #pragma unroll
                for (int mf = 0; mf < 4; mf++) {
                    mma_f16(acc[mf][np * 2 + 0], afr[mf], t[0], t[2]);
                    mma_f16(acc[mf][np * 2 + 1], afr[mf], t[1], t[3]);
                }
            }
        }
    }

    // epilogue: bias, route to Q/K/V fp16 [B,H,N,D]; Q scaled by log2e/32
    const int sec = f0 >> 10;
    const int bb_ = m0 >> 11;
    __half* dst = (sec == 0) ? g_q16 : (sec == 1) ? g_k16 : g_v16;
    const float sc = (sec == 0) ? QSCALE : 1.0f;
    float bv[4][2];
    #pragma unroll
    for (int nf = 0; nf < 4; nf++) {
        const int fc = f0 + wn * 32 + nf * 8 + qd;
        bv[nf][0] = bias[fc]; bv[nf][1] = bias[fc + 1];
    }
    #pragma unroll
    for (int mf = 0; mf < 4; mf++) {
        const int n0 = (m0 & (SEQ - 1)) + wm * 64 + mf * 16 + g;
        const int n1 = n0 + 8;
        #pragma unroll
        for (int nf = 0; nf < 4; nf++) {
            const int fc = f0 + wn * 32 + nf * 8 + qd;
            const int e = fc & (EMB - 1);
            const int hh = e >> 6, d = e & 63;
            const size_t i0 = (((size_t)(bb_ * HEADS + hh)) * SEQ + n0) * HDIM + d;
            const size_t i1 = (((size_t)(bb_ * HEADS + hh)) * SEQ + n1) * HDIM + d;
            *(uint32_t*)(dst + i0) = pack_h2((acc[mf][nf][0] + bv[nf][0]) * sc,
                                             (acc[mf][nf][1] + bv[nf][1]) * sc);
            *(uint32_t*)(dst + i1) = pack_h2((acc[mf][nf][2] + bv[nf][0]) * sc,
                                             (acc[mf][nf][3] + bv[nf][1]) * sc);
        }
    }
}

// ---------------- Attention: 64 q-rows/CTA, 4 warps, 2-stage, 4 CTAs/SM ----------------
#define AP_B 144                     // pitch: 72 fp16 = 144 B
#define AQ_B (64*AP_B)               // 9216 (Q, 64 rows)
#define KT_B (64*AP_B)               // 9216 per K or V stage
#define ATTN_SMEM (AQ_B + 4*KT_B)    // 46080
// layout: Q 0; K0 9216; K1 18432; V0 27648; V1 36864

__global__ __launch_bounds__(128, 4) void attn_mma(float* __restrict__ out) {
    extern __shared__ char sm[];
    const uint32_t sbase = smem_u32(sm);
    const int tid = threadIdx.x, lane = tid & 31, wid = tid >> 5;
    const int g = lane >> 2, qd = (lane & 3) * 2;
    const int b = blockIdx.z, h = blockIdx.y, q0 = blockIdx.x * 64;
    const size_t ho = ((size_t)(b * HEADS + h)) * SEQ * HDIM;
    const __half* qg = g_q16 + ho + (size_t)q0 * HDIM;
    const __half* kg = g_k16 + ho;
    const __half* vg = g_v16 + ho;

    auto load_tile = [&](int jt) {
        const int buf = jt & 1;
        const uint32_t Kb = sbase + AQ_B + buf * KT_B;
        const uint32_t Vb = sbase + AQ_B + 2 * KT_B + buf * KT_B;
        const int base = jt * 64;
        #pragma unroll
        for (int i = 0; i < 4; i++) {
            const int l = tid + i * 128;
            const int row = l >> 3, cc = l & 7;
            const size_t go = (size_t)(base + row) * HDIM + cc * 8;
            CP16(Kb + row * AP_B + cc * 16, kg + go);
            CP16(Vb + row * AP_B + cc * 16, vg + go);
        }
    };

    // Q (once) + tile 0 in one group
    #pragma unroll
    for (int i = 0; i < 4; i++) {
        const int l = tid + i * 128;
        const int row = l >> 3, cc = l & 7;
        CP16(sbase + row * AP_B + cc * 16, qg + (size_t)row * HDIM + cc * 8);
    }
    load_tile(0); CP_COMMIT();

    float o[8][4];
    #pragma unroll
    for (int nf = 0; nf < 8; nf++)
        #pragma unroll
        for (int e = 0; e < 4; e++) o[nf][e] = 0.f;
    float ls[4] = {0.f, 0.f, 0.f, 0.f};
    uint32_t qf[4][4];

    for (int jt = 0; jt < SEQ / 64; jt++) {
        CP_WAIT(0);
        __syncthreads();
        if (jt + 1 < SEQ / 64) { load_tile(jt + 1); CP_COMMIT(); }
        if (jt == 0) {
            #pragma unroll
            for (int kk = 0; kk < 4; kk++)
                ldsm4(qf[kk], sbase + (wid * 16 + (lane & 15)) * AP_B + kk * 32 + (lane >> 4) * 16);
        }
        const int buf = jt & 1;
        const uint32_t Kb = sbase + AQ_B + buf * KT_B;
        const uint32_t Vb = sbase + AQ_B + 2 * KT_B + buf * KT_B;

        // S = Q K^T
        float s[8][4];
        #pragma unroll
        for (int nf = 0; nf < 8; nf++)
            #pragma unroll
            for (int e = 0; e < 4; e++) s[nf][e] = 0.f;
        #pragma unroll
        for (int kk = 0; kk < 4; kk++) {
            #pragma unroll
            for (int np = 0; np < 4; np++) {
                uint32_t t[4];
                ldsm4(t, Kb + (np * 16 + (lane & 15)) * AP_B + kk * 32 + (lane >> 4) * 16);
                mma_f16(s[np * 2 + 0], qf[kk], t[0], t[2]);
                mma_f16(s[np * 2 + 1], qf[kk], t[1], t[3]);
            }
        }

        // p = 2^s packed fp16; lsum via ones-column mma; PV
        #pragma unroll
        for (int kk2 = 0; kk2 < 4; kk2++) {
            uint32_t ph[4];
            ph[0] = ex2h2(pack_h2(s[2 * kk2][0],     s[2 * kk2][1]));
            ph[1] = ex2h2(pack_h2(s[2 * kk2][2],     s[2 * kk2][3]));
            ph[2] = ex2h2(pack_h2(s[2 * kk2 + 1][0], s[2 * kk2 + 1][1]));
            ph[3] = ex2h2(pack_h2(s[2 * kk2 + 1][2], s[2 * kk2 + 1][3]));

            mma_f16(ls, ph, ONE2, ONE2);   // row sums of exactly the fp16 P used below

            const uint32_t vrow = (kk2 * 16 + (lane & 7) + ((lane >> 3) & 1) * 8) * AP_B;
            #pragma unroll
            for (int db = 0; db < 4; db++) {
                const uint32_t vcol = (db * 16 + (lane >> 4) * 8) * 2;
                uint32_t th[4];
                ldsm4t(th, Vb + vrow + vcol);
                mma_f16(o[db * 2 + 0], ph, th[0], th[1]);
                mma_f16(o[db * 2 + 1], ph, th[2], th[3]);
            }
        }
    }

    // ls[0] = full row sum for row g, ls[2] for row g+8
    const float inv0 = 1.0f / ls[0], inv1 = 1.0f / ls[2];
    const int r0 = q0 + wid * 16 + g;
    float* op0 = out + ((size_t)(b * SEQ + r0)) * EMB + h * HDIM;
    float* op1 = op0 + (size_t)8 * EMB;
    #pragma unroll
    for (int nf = 0; nf < 8; nf++) {
        const int d = nf * 8 + qd;
        float2 v;
        v.x = o[nf][0] * inv0; v.y = o[nf][1] * inv0;
        *(float2*)(op0 + d) = v;
        v.x = o[nf][2] * inv1; v.y = o[nf][3] * inv1;
        *(float2*)(op1 + d) = v;
    }
}

// ---------------- launcher ----------------
extern "C" void kernel_launch(void* const* d_in, const int* in_sizes, int n_in,
                              void* d_out, int out_size)
{
    const float* x    = (const float*)d_in[0];
    const float* w    = (const float*)d_in[1];
    const float* bias = (const float*)d_in[2];
    float* out = (float*)d_out;

    cvt_x<<<XN / 512, 256>>>(x);
    cvt_w<<<WN / 512, 256>>>(w);

    cudaFuncSetAttribute(qkv_gemm_mma, cudaFuncAttributeMaxDynamicSharedMemorySize, GEMM_SMEM);
    dim3 g1(F3 / 64, MROWS / 128);    // (48, 32)
    qkv_gemm_mma<<<g1, 128, GEMM_SMEM>>>(bias);

    cudaFuncSetAttribute(attn_mma, cudaFuncAttributeMaxDynamicSharedMemorySize, ATTN_SMEM);
    dim3 g2(SEQ / 64, HEADS, BATCH);  // (32, 16, 2)
    attn_mma<<<g2, 128, ATTN_SMEM>>>(out);
}